// round 9
// baseline (speedup 1.0000x reference)
#include <cuda_runtime.h>
#include <cstdint>
#include <math.h>

#define B_  8
#define T_  2048
#define C_  1024
#define H_  1024
#define SCALE_ (1.0f / 32.0f)

// GEMM tiling: CTA 128x128, 4 warps (2m x 2n), warp 64x64  (R7 shape)
#define BM 128
#define BN 128
#define BK 32
#define NTHR 128
#define A_ST_BYTES 16384
#define STAGE_BYTES 32768
#define NSTAGES 3
#define SMEM_TOTAL (STAGE_BYTES * NSTAGES)   // 98304 -> 2 CTAs/SM

// 16-group interleave (involution): orig k -> stored ((k&3)<<2)|(k>>2)
__host__ __device__ __forceinline__ int p16(int k) {
    return (k & ~15) | (((k & 3) << 2) | ((k & 15) >> 2));
}

// ---------------------------------------------------------------------------
// Scratch — contraction dims stored p16-interleaved.
// g_K rows (t) additionally p16'd so S lands pre-interleaved for pv.
// ---------------------------------------------------------------------------
__device__ float g_X  [(size_t)B_ * T_ * C_];
__device__ float g_Q  [(size_t)B_ * T_ * H_];
__device__ float g_K  [(size_t)B_ * T_ * H_];
__device__ float g_V  [(size_t)B_ * T_ * H_];
__device__ float g_VT [(size_t)B_ * H_ * T_];
__device__ float g_S  [(size_t)B_ * T_ * T_];
__device__ float g_WT [3][(size_t)H_ * C_];
__device__ float g_sum[(size_t)B_ * T_];

// ---------------------------------------------------------------------------
// Helpers
// ---------------------------------------------------------------------------
__device__ __forceinline__ uint32_t f2tf32(float f) {
    uint32_t r;
    asm("cvt.rna.tf32.f32 %0, %1;" : "=r"(r) : "f"(f));
    return r;
}
__device__ __forceinline__ float round_tf32(float f) {
    return __uint_as_float(f2tf32(f));
}
__device__ __forceinline__ void mma_tf32(float c[4], uint32_t a0, uint32_t a1,
                                         uint32_t a2, uint32_t a3,
                                         uint32_t b0, uint32_t b1) {
    asm volatile(
        "mma.sync.aligned.m16n8k8.row.col.f32.tf32.tf32.f32 "
        "{%0,%1,%2,%3}, {%4,%5,%6,%7}, {%8,%9}, {%0,%1,%2,%3};"
        : "+f"(c[0]), "+f"(c[1]), "+f"(c[2]), "+f"(c[3])
        : "r"(a0), "r"(a1), "r"(a2), "r"(a3), "r"(b0), "r"(b1));
}
__device__ __forceinline__ void cp16(uint32_t d, const void* s) {
    asm volatile("cp.async.cg.shared.global [%0], [%1], 16;" :: "r"(d), "l"(s));
}
__device__ __forceinline__ void cp_commit() { asm volatile("cp.async.commit_group;"); }
__device__ __forceinline__ void cp_wait1()  { asm volatile("cp.async.wait_group 1;"); }
__device__ __forceinline__ void cp_wait0()  { asm volatile("cp.async.wait_group 0;"); }

// ---------------------------------------------------------------------------
// GEMM core. MODE 0: plain; MODE 1: qk fused softmax; MODE 2: pv deferred norm
// 128 thr, 4 warps (2m x 2n, warp 64x64), 3-stage cp.async, single sync/tile,
// LDS.128 fragment loads via p16 interleave, swizzle col^=(row&1)<<4.
// ---------------------------------------------------------------------------
template<int MODE>
__device__ __forceinline__ void gemm_core(const float* __restrict__ Ag, int lda,
                                          const float* __restrict__ Bg, int ldb,
                                          float* __restrict__ Cg, int ldc,
                                          int nt, float scale,
                                          const float* __restrict__ rowsum,
                                          float* __restrict__ sumatomic,
                                          int gq0, int gn0,
                                          bool round_out, bool permute_rows)
{
    extern __shared__ char dynsmem[];
    const int tid  = threadIdx.x;
    const int lane = tid & 31;
    const int wid  = tid >> 5;
    const int wm   = wid & 1;
    const int wn   = wid >> 1;
    const int g    = lane >> 2;
    const int t    = lane & 3;

    const uint32_t sb = (uint32_t)__cvta_generic_to_shared(dynsmem);
    const int r0 = tid >> 3;            // 0..15
    const int c4 = (tid & 7) << 2;      // word col 0..28

    auto issue = [&](int s, int buf) {
        const float* Abase = Ag + (size_t)s * BK;
        const float* Bbase = Bg + (size_t)s * BK;
        const uint32_t ab = sb + buf * STAGE_BYTES;
        const uint32_t bb = ab + A_ST_BYTES;
        #pragma unroll
        for (int i = 0; i < 8; i++) {
            const int r  = r0 + 16 * i;
            const int sc = c4 ^ ((r & 1) << 4);
            cp16(ab + r * 128 + sc * 4, Abase + (size_t)r * lda + c4);
            cp16(bb + r * 128 + sc * 4, Bbase + (size_t)r * ldb + c4);
        }
        cp_commit();
    };

    float acc[4][8][4];
    #pragma unroll
    for (int i = 0; i < 4; i++)
        #pragma unroll
        for (int j = 0; j < 8; j++)
            #pragma unroll
            for (int r = 0; r < 4; r++) acc[i][j][r] = 0.0f;

    issue(0, 0);
    issue(1, 1);

    const int mwb = wm * 64;
    const int nwb = wn * 64;
    const int swz = (g & 1) << 4;

    cp_wait1();
    __syncthreads();

    for (int s = 0; s < nt; s++) {
        if (s + 2 < nt) issue(s + 2, (s + 2) % NSTAGES);

        const uint32_t* As = (const uint32_t*)(dynsmem + (s % NSTAGES) * STAGE_BYTES);
        const uint32_t* Bs = (const uint32_t*)(dynsmem + (s % NSTAGES) * STAGE_BYTES + A_ST_BYTES);

        #pragma unroll
        for (int kk16 = 0; kk16 < 2; kk16++) {
            const int cw = (kk16 * 16 + 4 * t) ^ swz;
            uint4 alo[4], ahi[4], bv[8];
            #pragma unroll
            for (int mf = 0; mf < 4; mf++) {
                const int rA = mwb + mf * 16 + g;
                alo[mf] = *(const uint4*)&As[rA * 32 + cw];
                ahi[mf] = *(const uint4*)&As[(rA + 8) * 32 + cw];
            }
            #pragma unroll
            for (int nf = 0; nf < 8; nf++) {
                const int rB = nwb + nf * 8 + g;
                bv[nf] = *(const uint4*)&Bs[rB * 32 + cw];
            }
            // substep 0: orig k = {t, t+4}
            #pragma unroll
            for (int mf = 0; mf < 4; mf++)
                #pragma unroll
                for (int nf = 0; nf < 8; nf++)
                    mma_tf32(acc[mf][nf], alo[mf].x, ahi[mf].x, alo[mf].y, ahi[mf].y,
                             bv[nf].x, bv[nf].y);
            // substep 1: orig k = {t+8, t+12}
            #pragma unroll
            for (int mf = 0; mf < 4; mf++)
                #pragma unroll
                for (int nf = 0; nf < 8; nf++)
                    mma_tf32(acc[mf][nf], alo[mf].z, ahi[mf].z, alo[mf].w, ahi[mf].w,
                             bv[nf].z, bv[nf].w);
        }

        if (s + 1 < nt) {
            cp_wait1();
            __syncthreads();
        }
    }

    // ---- Epilogue ----
    #pragma unroll
    for (int mf = 0; mf < 4; mf++) {
        const int row = mwb + mf * 16 + g;   // low4 == g

        if (MODE == 1) {
            const int gq = gq0 + row;
            float rs0 = 0.0f, rs1 = 0.0f;
            #pragma unroll
            for (int nf = 0; nf < 8; nf++) {
                const int col = nwb + nf * 8 + 2 * t;
                const int jl  = (nf & 1) * 8 + 2 * t;
                const int gk0 = gn0 + nwb + (nf & ~1) * 8 + ((jl & 3) << 2) + (jl >> 2);
                const int gk1 = gk0 + 4;
                float e0 = (gq     >= gk0) ? __expf(acc[mf][nf][0] * scale) : 0.0f;
                float e1 = (gq     >= gk1) ? __expf(acc[mf][nf][1] * scale) : 0.0f;
                float e2 = (gq + 8 >= gk0) ? __expf(acc[mf][nf][2] * scale) : 0.0f;
                float e3 = (gq + 8 >= gk1) ? __expf(acc[mf][nf][3] * scale) : 0.0f;
                rs0 += e0 + e1;
                rs1 += e2 + e3;
                *(float2*)&Cg[(size_t)row * ldc + col] =
                    make_float2(round_tf32(e0), round_tf32(e1));
                *(float2*)&Cg[(size_t)(row + 8) * ldc + col] =
                    make_float2(round_tf32(e2), round_tf32(e3));
            }
            rs0 += __shfl_xor_sync(0xFFFFFFFFu, rs0, 1);
            rs0 += __shfl_xor_sync(0xFFFFFFFFu, rs0, 2);
            rs1 += __shfl_xor_sync(0xFFFFFFFFu, rs1, 1);
            rs1 += __shfl_xor_sync(0xFFFFFFFFu, rs1, 2);
            if (t == 0) {
                atomicAdd(&sumatomic[row], rs0);
                atomicAdd(&sumatomic[row + 8], rs1);
            }
        } else {
            float s0 = scale, s1 = scale;
            if (MODE == 2) {
                s0 = 1.0f / rowsum[row];
                s1 = 1.0f / rowsum[row + 8];
            }
            int rw0 = row, rw1 = row + 8;
            if (MODE == 0 && permute_rows) {   // K output: t-rows p16'd
                rw0 = (row & ~15) | (((g & 3) << 2) | (g >> 2));
                rw1 = rw0 + 2;                 // p16(g+8) = p16(g) + 2
            }
            #pragma unroll
            for (int nf = 0; nf < 8; nf++) {
                const int col = nwb + nf * 8 + 2 * t;
                float v0 = acc[mf][nf][0] * s0, v1 = acc[mf][nf][1] * s0;
                float v2 = acc[mf][nf][2] * s1, v3 = acc[mf][nf][3] * s1;
                if (round_out) {
                    v0 = round_tf32(v0); v1 = round_tf32(v1);
                    v2 = round_tf32(v2); v3 = round_tf32(v3);
                }
                *(float2*)&Cg[(size_t)rw0 * ldc + col] = make_float2(v0, v1);
                *(float2*)&Cg[(size_t)rw1 * ldc + col] = make_float2(v2, v3);
            }
        }
    }
}

// ---------------------------------------------------------------------------
// GEMM wrappers
// ---------------------------------------------------------------------------
__global__ __launch_bounds__(NTHR, 2)
void proj_mma(const float* __restrict__ W0, const float* __restrict__ W1,
              const float* __restrict__ W2)
{
    const int z = blockIdx.z;
    const float* WT = (z == 0) ? W0 : (z == 1) ? W1 : W2;
    float* out = (z == 0) ? g_Q : (z == 1) ? g_K : g_V;
    const size_t m0 = (size_t)blockIdx.y * BM;
    const size_t n0 = (size_t)blockIdx.x * BN;
    gemm_core<0>(g_X + m0 * C_, C_, WT + n0 * C_, C_,
                 out + m0 * H_ + n0, H_, C_ / BK, 1.0f,
                 nullptr, nullptr, 0, 0, true, z == 1);
}

__global__ __launch_bounds__(NTHR, 2)
void qk_mma()
{
    const int kb = blockIdx.x;
    const int qb = gridDim.y - 1 - blockIdx.y;   // big tiles first
    if (kb > qb) return;
    const int b = blockIdx.z;
    const size_t q0 = (size_t)qb * 128, n0 = (size_t)kb * 128;
    gemm_core<1>(g_Q + (size_t)b * T_ * H_ + q0 * H_, H_,
                 g_K + (size_t)b * T_ * H_ + n0 * H_, H_,
                 g_S + (size_t)b * T_ * T_ + q0 * T_ + n0, T_,
                 H_ / BK, SCALE_,
                 nullptr, g_sum + (size_t)b * T_ + q0, (int)q0, (int)n0,
                 false, false);
}

__global__ __launch_bounds__(NTHR, 2)
void pv_mma(float* __restrict__ out)
{
    const int nb = blockIdx.x;
    const int qb = gridDim.y - 1 - blockIdx.y;   // big tiles first
    const int b  = blockIdx.z;
    const size_t q0 = (size_t)qb * 128, n0 = (size_t)nb * 128;
    gemm_core<2>(g_S  + (size_t)b * T_ * T_ + q0 * T_, T_,
                 g_VT + (size_t)b * H_ * T_ + n0 * T_, T_,
                 out + (size_t)b * T_ * H_ + q0 * H_ + n0, H_,
                 (qb + 1) * 4, 1.0f,
                 g_sum + (size_t)b * T_ + q0, nullptr, 0, 0,
                 false, false);
}

// ---------------------------------------------------------------------------
// x -> tf32-rounded, C-dim p16-interleaved
// ---------------------------------------------------------------------------
__global__ __launch_bounds__(256)
void cvt_x(const float* __restrict__ in)
{
    const size_t i = ((size_t)blockIdx.x * 256 + threadIdx.x) * 4;
    float4 v = *(const float4*)(in + i);
    const size_t base16 = i & ~(size_t)15;
    const int a = (int)((i & 15) >> 2);   // 0..3
    g_X[base16 + 0 + a]  = round_tf32(v.x);
    g_X[base16 + 4 + a]  = round_tf32(v.y);
    g_X[base16 + 8 + a]  = round_tf32(v.z);
    g_X[base16 + 12 + a] = round_tf32(v.w);
}

__global__ __launch_bounds__(256)
void zero_sums()
{
    g_sum[(size_t)blockIdx.x * 256 + threadIdx.x] = 0.0f;
}

// ---------------------------------------------------------------------------
// W transposes: [C,H] -> [H,C]; C cols p16. For Wq/Wk the h ROW also p16'd.
// ---------------------------------------------------------------------------
__global__ __launch_bounds__(256)
void transpose_w(const float* __restrict__ Wq, const float* __restrict__ Wk,
                 const float* __restrict__ Wv)
{
    __shared__ float tile[32][33];
    const int z = blockIdx.z;
    const float* I = (z == 0) ? Wq : (z == 1) ? Wk : Wv;
    float* O = g_WT[z];
    const int r0 = blockIdx.y * 32, c0 = blockIdx.x * 32;   // r: C, c: H
    const int tx = threadIdx.x & 31, ty = threadIdx.x >> 5;
    #pragma unroll
    for (int i = 0; i < 32; i += 8)
        tile[ty + i][tx] = I[(size_t)(r0 + ty + i) * H_ + c0 + tx];
    __syncthreads();
    const int fp = p16(r0 + tx);
    #pragma unroll
    for (int i = 0; i < 32; i += 8) {
        const int hr = (z < 2) ? p16(i + ty) : (i + ty);
        O[(size_t)(c0 + hr) * C_ + fp] = round_tf32(tile[tx][ty + i]);
    }
}

// ---------------------------------------------------------------------------
// V transpose per batch: [T,H] -> [H,T]; T cols p16
// ---------------------------------------------------------------------------
__global__ __launch_bounds__(256)
void transpose_v()
{
    __shared__ float tile[32][33];
    const int z = blockIdx.z;
    const float* I = g_V  + (size_t)z * T_ * H_;
    float*       O = g_VT + (size_t)z * H_ * T_;
    const int r0 = blockIdx.y * 32, c0 = blockIdx.x * 32;
    const int tx = threadIdx.x & 31, ty = threadIdx.x >> 5;
    #pragma unroll
    for (int i = 0; i < 32; i += 8)
        tile[ty + i][tx] = I[(size_t)(r0 + ty + i) * H_ + c0 + tx];
    __syncthreads();
    const int fp = p16(r0 + tx);
    #pragma unroll
    for (int i = 0; i < 32; i += 8)
        O[(size_t)(c0 + ty + i) * T_ + fp] = tile[tx][ty + i];
}

// ---------------------------------------------------------------------------
// Launch
// ---------------------------------------------------------------------------
extern "C" void kernel_launch(void* const* d_in, const int* in_sizes, int n_in,
                              void* d_out, int out_size)
{
    const float* x  = (const float*)d_in[0];
    const float* Wq = (const float*)d_in[1];
    const float* Wk = (const float*)d_in[2];
    const float* Wv = (const float*)d_in[3];
    float* out = (float*)d_out;

    float* wtp;
    cudaGetSymbolAddress((void**)&wtp, g_WT);

    cudaFuncSetAttribute(proj_mma, cudaFuncAttributeMaxDynamicSharedMemorySize, SMEM_TOTAL);
    cudaFuncSetAttribute(qk_mma,   cudaFuncAttributeMaxDynamicSharedMemorySize, SMEM_TOTAL);
    cudaFuncSetAttribute(pv_mma,   cudaFuncAttributeMaxDynamicSharedMemorySize, SMEM_TOTAL);

    cvt_x<<<(B_ * T_ * C_) / (256 * 4), 256>>>(x);
    zero_sums<<<(B_ * T_) / 256, 256>>>();

    dim3 gtw(H_ / 32, C_ / 32, 3);
    transpose_w<<<gtw, 256>>>(Wq, Wk, Wv);

    dim3 gproj(H_ / BN, (B_ * T_) / BM, 3);
    proj_mma<<<gproj, NTHR, SMEM_TOTAL>>>(
        wtp, wtp + (size_t)H_ * C_, wtp + 2 * (size_t)H_ * C_);

    dim3 gtv(H_ / 32, T_ / 32, B_);
    transpose_v<<<gtv, 256>>>();

    dim3 gqk(T_ / 128, T_ / 128, B_);
    qk_mma<<<gqk, NTHR, SMEM_TOTAL>>>();

    dim3 gpv(H_ / 128, T_ / 128, B_);
    pv_mma<<<gpv, NTHR, SMEM_TOTAL>>>(out);
}

// round 10
// speedup vs baseline: 1.5656x; 1.5656x over previous
#include <cuda_runtime.h>
#include <cstdint>
#include <math.h>

#define B_  8
#define T_  2048
#define C_  1024
#define H_  1024
#define SCALE_ (1.0f / 32.0f)

// GEMM tiling: CTA 128x128, 4 warps (2m x 2n), warp 64x64 (R7 shape)
#define BM 128
#define BN 128
#define BK 32
#define NTHR 128
#define A_ST_BYTES 16384
#define STAGE_BYTES 32768
#define NSTAGES 2
#define SMEM_TOTAL (STAGE_BYTES * NSTAGES)   // 65536 -> 3 CTAs/SM

__host__ __device__ __forceinline__ int kperm(int k) {   // pair-perm within 8
    return (k & ~7) | (((k & 3) << 1) | ((k & 7) >> 2));
}

// ---------------------------------------------------------------------------
// Scratch — operands stored K-pair-permuted along contraction dims.
// g_K rows (t) additionally kperm'd so S lands pre-permuted for pv.
// ---------------------------------------------------------------------------
__device__ float g_X  [(size_t)B_ * T_ * C_];
__device__ float g_Q  [(size_t)B_ * T_ * H_];
__device__ float g_K  [(size_t)B_ * T_ * H_];
__device__ float g_V  [(size_t)B_ * T_ * H_];
__device__ float g_VT [(size_t)B_ * H_ * T_];
__device__ float g_S  [(size_t)B_ * T_ * T_];
__device__ float g_WT [3][(size_t)H_ * C_];
__device__ float g_sum[(size_t)B_ * T_];

// ---------------------------------------------------------------------------
// Helpers
// ---------------------------------------------------------------------------
__device__ __forceinline__ uint32_t f2tf32(float f) {
    uint32_t r;
    asm("cvt.rna.tf32.f32 %0, %1;" : "=r"(r) : "f"(f));
    return r;
}
__device__ __forceinline__ float round_tf32(float f) {
    return __uint_as_float(f2tf32(f));
}
__device__ __forceinline__ void mma_tf32(float c[4], const uint32_t a[4],
                                         const uint32_t b[2]) {
    asm volatile(
        "mma.sync.aligned.m16n8k8.row.col.f32.tf32.tf32.f32 "
        "{%0,%1,%2,%3}, {%4,%5,%6,%7}, {%8,%9}, {%0,%1,%2,%3};"
        : "+f"(c[0]), "+f"(c[1]), "+f"(c[2]), "+f"(c[3])
        : "r"(a[0]), "r"(a[1]), "r"(a[2]), "r"(a[3]), "r"(b[0]), "r"(b[1]));
}
__device__ __forceinline__ void cp16(uint32_t d, const void* s) {
    asm volatile("cp.async.cg.shared.global [%0], [%1], 16;" :: "r"(d), "l"(s));
}
__device__ __forceinline__ void cp_commit() { asm volatile("cp.async.commit_group;"); }
__device__ __forceinline__ void cp_wait1()  { asm volatile("cp.async.wait_group 1;"); }
__device__ __forceinline__ void cp_wait0()  { asm volatile("cp.async.wait_group 0;"); }

// ---------------------------------------------------------------------------
// GEMM core. MODE 0: plain; MODE 1: qk fused softmax; MODE 2: pv deferred norm
// 128 thr, 4 warps (2m x 2n, warp 64x64), 2-stage cp.async (3 CTAs/SM),
// single-buffered fragments, swizzled 32-word rows, LDS.64 frag loads.
// ---------------------------------------------------------------------------
template<int MODE>
__device__ __forceinline__ void gemm_core(const float* __restrict__ Ag, int lda,
                                          const float* __restrict__ Bg, int ldb,
                                          float* __restrict__ Cg, int ldc,
                                          int nt, float scale,
                                          const float* __restrict__ rowsum,
                                          float* __restrict__ sumatomic,
                                          int gq0, int gn0,
                                          bool round_out, bool permute_rows)
{
    extern __shared__ char dynsmem[];
    const int tid  = threadIdx.x;
    const int lane = tid & 31;
    const int wid  = tid >> 5;
    const int wm   = wid & 1;
    const int wn   = wid >> 1;
    const int g    = lane >> 2;
    const int t    = lane & 3;

    const uint32_t sb = (uint32_t)__cvta_generic_to_shared(dynsmem);
    const int r0 = tid >> 3;            // 0..15
    const int c4 = (tid & 7) << 2;      // word col 0..28

    auto issue = [&](int s, int buf) {
        const float* Abase = Ag + (size_t)s * BK;
        const float* Bbase = Bg + (size_t)s * BK;
        const uint32_t ab = sb + buf * STAGE_BYTES;
        const uint32_t bb = ab + A_ST_BYTES;
        #pragma unroll
        for (int i = 0; i < 8; i++) {
            const int r  = r0 + 16 * i;
            const int sc = c4 ^ ((r & 3) << 3);
            cp16(ab + r * 128 + sc * 4, Abase + (size_t)r * lda + c4);
            cp16(bb + r * 128 + sc * 4, Bbase + (size_t)r * ldb + c4);
        }
        cp_commit();
    };

    float acc[4][8][4];
    #pragma unroll
    for (int i = 0; i < 4; i++)
        #pragma unroll
        for (int j = 0; j < 8; j++)
            #pragma unroll
            for (int r = 0; r < 4; r++) acc[i][j][r] = 0.0f;

    issue(0, 0);
    if (nt > 1) issue(1, 1);

    const int mwb = wm * 64;
    const int nwb = wn * 64;
    const int swz = (g & 3) << 3;

    for (int s = 0; s < nt; s++) {
        if (s + 1 < nt) cp_wait1(); else cp_wait0();
        __syncthreads();   // buffer s ready

        const uint32_t* As = (const uint32_t*)(dynsmem + (s & 1) * STAGE_BYTES);
        const uint32_t* Bs = (const uint32_t*)(dynsmem + (s & 1) * STAGE_BYTES + A_ST_BYTES);

        #pragma unroll
        for (int kk8 = 0; kk8 < 4; kk8++) {
            const int cw = (kk8 * 8 + 2 * t) ^ swz;
            uint32_t ar[4][4];
            #pragma unroll
            for (int mf = 0; mf < 4; mf++) {
                const int rA = mwb + mf * 16 + g;
                uint2 v0 = *(const uint2*)&As[rA * 32 + cw];
                uint2 v1 = *(const uint2*)&As[(rA + 8) * 32 + cw];
                ar[mf][0] = v0.x; ar[mf][2] = v0.y;
                ar[mf][1] = v1.x; ar[mf][3] = v1.y;
            }
            uint32_t br[8][2];
            #pragma unroll
            for (int nf = 0; nf < 8; nf++) {
                const int rB = nwb + nf * 8 + g;
                uint2 v = *(const uint2*)&Bs[rB * 32 + cw];
                br[nf][0] = v.x; br[nf][1] = v.y;
            }
            #pragma unroll
            for (int mf = 0; mf < 4; mf++)
                #pragma unroll
                for (int nf = 0; nf < 8; nf++)
                    mma_tf32(acc[mf][nf], ar[mf], br[nf]);
        }

        __syncthreads();   // all warps done with buffer s
        if (s + 2 < nt) issue(s + 2, s & 1);
    }

    // ---- Epilogue (vectorized float2) ----
    #pragma unroll
    for (int mf = 0; mf < 4; mf++) {
        const int row = mwb + mf * 16 + g;

        if (MODE == 1) {
            // exp + causal mask (S cols pre-permuted: orig key of col 2t is t,
            // of col 2t+1 is t+4)
            const int gq = gq0 + row;
            float rs0 = 0.0f, rs1 = 0.0f;
            #pragma unroll
            for (int nf = 0; nf < 8; nf++) {
                const int col = nwb + nf * 8 + 2 * t;
                const int gk0 = gn0 + nwb + nf * 8 + t;
                const int gk1 = gk0 + 4;
                float e0 = (gq     >= gk0) ? __expf(acc[mf][nf][0] * scale) : 0.0f;
                float e1 = (gq     >= gk1) ? __expf(acc[mf][nf][1] * scale) : 0.0f;
                float e2 = (gq + 8 >= gk0) ? __expf(acc[mf][nf][2] * scale) : 0.0f;
                float e3 = (gq + 8 >= gk1) ? __expf(acc[mf][nf][3] * scale) : 0.0f;
                rs0 += e0 + e1;
                rs1 += e2 + e3;
                *(float2*)&Cg[(size_t)row * ldc + col] =
                    make_float2(round_tf32(e0), round_tf32(e1));
                *(float2*)&Cg[(size_t)(row + 8) * ldc + col] =
                    make_float2(round_tf32(e2), round_tf32(e3));
            }
            rs0 += __shfl_xor_sync(0xFFFFFFFFu, rs0, 1);
            rs0 += __shfl_xor_sync(0xFFFFFFFFu, rs0, 2);
            rs1 += __shfl_xor_sync(0xFFFFFFFFu, rs1, 1);
            rs1 += __shfl_xor_sync(0xFFFFFFFFu, rs1, 2);
            if (t == 0) {
                atomicAdd(&sumatomic[row], rs0);
                atomicAdd(&sumatomic[row + 8], rs1);
            }
        } else {
            float s0 = scale, s1 = scale;
            if (MODE == 2) {
                s0 = 1.0f / rowsum[row];
                s1 = 1.0f / rowsum[row + 8];
            }
            int rw0 = row, rw1 = row + 8;
            if (MODE == 0 && permute_rows) {     // K output: t-rows kperm'd
                rw0 = (row - g) + kperm(g);
                rw1 = rw0 + 8;
            }
            #pragma unroll
            for (int nf = 0; nf < 8; nf++) {
                const int col = nwb + nf * 8 + 2 * t;
                float v0 = acc[mf][nf][0] * s0, v1 = acc[mf][nf][1] * s0;
                float v2 = acc[mf][nf][2] * s1, v3 = acc[mf][nf][3] * s1;
                if (round_out) {
                    v0 = round_tf32(v0); v1 = round_tf32(v1);
                    v2 = round_tf32(v2); v3 = round_tf32(v3);
                }
                *(float2*)&Cg[(size_t)rw0 * ldc + col] = make_float2(v0, v1);
                *(float2*)&Cg[(size_t)rw1 * ldc + col] = make_float2(v2, v3);
            }
        }
    }
}

// ---------------------------------------------------------------------------
// GEMM wrappers
// ---------------------------------------------------------------------------
__global__ __launch_bounds__(NTHR, 3)
void proj_mma(const float* __restrict__ W0, const float* __restrict__ W1,
              const float* __restrict__ W2)
{
    const int z = blockIdx.z;
    const float* WT = (z == 0) ? W0 : (z == 1) ? W1 : W2;
    float* out = (z == 0) ? g_Q : (z == 1) ? g_K : g_V;
    const size_t m0 = (size_t)blockIdx.y * BM;
    const size_t n0 = (size_t)blockIdx.x * BN;
    gemm_core<0>(g_X + m0 * C_, C_, WT + n0 * C_, C_,
                 out + m0 * H_ + n0, H_, C_ / BK, 1.0f,
                 nullptr, nullptr, 0, 0, true, z == 1);
}

__global__ __launch_bounds__(NTHR, 3)
void qk_mma()
{
    const int kb = blockIdx.x;
    const int qb = gridDim.y - 1 - blockIdx.y;   // big tiles first
    if (kb > qb) return;
    const int b = blockIdx.z;
    const size_t q0 = (size_t)qb * 128, n0 = (size_t)kb * 128;
    gemm_core<1>(g_Q + (size_t)b * T_ * H_ + q0 * H_, H_,
                 g_K + (size_t)b * T_ * H_ + n0 * H_, H_,
                 g_S + (size_t)b * T_ * T_ + q0 * T_ + n0, T_,
                 H_ / BK, SCALE_,
                 nullptr, g_sum + (size_t)b * T_ + q0, (int)q0, (int)n0,
                 false, false);
}

__global__ __launch_bounds__(NTHR, 3)
void pv_mma(float* __restrict__ out)
{
    const int nb = blockIdx.x;
    const int qb = gridDim.y - 1 - blockIdx.y;   // big tiles first
    const int b  = blockIdx.z;
    const size_t q0 = (size_t)qb * 128, n0 = (size_t)nb * 128;
    gemm_core<2>(g_S  + (size_t)b * T_ * T_ + q0 * T_, T_,
                 g_VT + (size_t)b * H_ * T_ + n0 * T_, T_,
                 out + (size_t)b * T_ * H_ + q0 * H_ + n0, H_,
                 (qb + 1) * 4, 1.0f,
                 g_sum + (size_t)b * T_ + q0, nullptr, 0, 0,
                 false, false);
}

// ---------------------------------------------------------------------------
// x -> tf32-rounded, C-pair-permuted copy
// ---------------------------------------------------------------------------
__global__ __launch_bounds__(256)
void cvt_x(const float* __restrict__ in)
{
    const size_t i = ((size_t)blockIdx.x * 256 + threadIdx.x) * 4;
    float4 v = *(const float4*)(in + i);
    const size_t base = i & ~(size_t)7;
    const int k0 = (int)(i & 7);
    g_X[base + kperm(k0 + 0)] = round_tf32(v.x);
    g_X[base + kperm(k0 + 1)] = round_tf32(v.y);
    g_X[base + kperm(k0 + 2)] = round_tf32(v.z);
    g_X[base + kperm(k0 + 3)] = round_tf32(v.w);
}

__global__ __launch_bounds__(256)
void zero_sums()
{
    g_sum[(size_t)blockIdx.x * 256 + threadIdx.x] = 0.0f;
}

// ---------------------------------------------------------------------------
// W transposes: [C,H] -> [H,C]. C cols pair-permuted; Wq/Wk h rows kperm'd.
// ---------------------------------------------------------------------------
__global__ __launch_bounds__(256)
void transpose_w(const float* __restrict__ Wq, const float* __restrict__ Wk,
                 const float* __restrict__ Wv)
{
    __shared__ float tile[32][33];
    const int z = blockIdx.z;
    const float* I = (z == 0) ? Wq : (z == 1) ? Wk : Wv;
    float* O = g_WT[z];
    const int r0 = blockIdx.y * 32, c0 = blockIdx.x * 32;   // r: C, c: H
    const int tx = threadIdx.x & 31, ty = threadIdx.x >> 5;
    #pragma unroll
    for (int i = 0; i < 32; i += 8)
        tile[ty + i][tx] = I[(size_t)(r0 + ty + i) * H_ + c0 + tx];
    __syncthreads();
    const int fp = kperm(r0 + tx);
    const int hp = (z < 2) ? kperm(ty) : ty;   // h low3 == ty
    #pragma unroll
    for (int i = 0; i < 32; i += 8)
        O[(size_t)(c0 + i + hp) * C_ + fp] = round_tf32(tile[tx][ty + i]);
}

// ---------------------------------------------------------------------------
// V transpose per batch: [T,H] -> [H,T], T cols pair-permuted
// ---------------------------------------------------------------------------
__global__ __launch_bounds__(256)
void transpose_v()
{
    __shared__ float tile[32][33];
    const int z = blockIdx.z;
    const float* I = g_V  + (size_t)z * T_ * H_;
    float*       O = g_VT + (size_t)z * H_ * T_;
    const int r0 = blockIdx.y * 32, c0 = blockIdx.x * 32;
    const int tx = threadIdx.x & 31, ty = threadIdx.x >> 5;
    #pragma unroll
    for (int i = 0; i < 32; i += 8)
        tile[ty + i][tx] = I[(size_t)(r0 + ty + i) * H_ + c0 + tx];
    __syncthreads();
    const int fp = kperm(r0 + tx);
    #pragma unroll
    for (int i = 0; i < 32; i += 8)
        O[(size_t)(c0 + ty + i) * T_ + fp] = tile[tx][ty + i];
}

// ---------------------------------------------------------------------------
// Launch
// ---------------------------------------------------------------------------
extern "C" void kernel_launch(void* const* d_in, const int* in_sizes, int n_in,
                              void* d_out, int out_size)
{
    const float* x  = (const float*)d_in[0];
    const float* Wq = (const float*)d_in[1];
    const float* Wk = (const float*)d_in[2];
    const float* Wv = (const float*)d_in[3];
    float* out = (float*)d_out;

    float* wtp;
    cudaGetSymbolAddress((void**)&wtp, g_WT);

    cudaFuncSetAttribute(proj_mma, cudaFuncAttributeMaxDynamicSharedMemorySize, SMEM_TOTAL);
    cudaFuncSetAttribute(qk_mma,   cudaFuncAttributeMaxDynamicSharedMemorySize, SMEM_TOTAL);
    cudaFuncSetAttribute(pv_mma,   cudaFuncAttributeMaxDynamicSharedMemorySize, SMEM_TOTAL);

    cvt_x<<<(B_ * T_ * C_) / (256 * 4), 256>>>(x);
    zero_sums<<<(B_ * T_) / 256, 256>>>();

    dim3 gtw(H_ / 32, C_ / 32, 3);
    transpose_w<<<gtw, 256>>>(Wq, Wk, Wv);

    dim3 gproj(H_ / BN, (B_ * T_) / BM, 3);
    proj_mma<<<gproj, NTHR, SMEM_TOTAL>>>(
        wtp, wtp + (size_t)H_ * C_, wtp + 2 * (size_t)H_ * C_);

    dim3 gtv(H_ / 32, T_ / 32, B_);
    transpose_v<<<gtv, 256>>>();

    dim3 gqk(T_ / 128, T_ / 128, B_);
    qk_mma<<<gqk, NTHR, SMEM_TOTAL>>>();

    dim3 gpv(H_ / 128, T_ / 128, B_);
    pv_mma<<<gpv, NTHR, SMEM_TOTAL>>>(out);
}

// round 11
// speedup vs baseline: 1.5793x; 1.0088x over previous
#include <cuda_runtime.h>
#include <cstdint>
#include <math.h>

#define B_  8
#define T_  2048
#define C_  1024
#define H_  1024
#define SCALE_ (1.0f / 32.0f)

// GEMM tiling: CTA 128x128, 4 warps (2m x 2n), warp 64x64
#define BM 128
#define BN 128
#define BK 32
#define NTHR 128
#define A_ST_BYTES 16384
#define STAGE_BYTES 32768
#define NSTAGES 2
#define SMEM_TOTAL (STAGE_BYTES * NSTAGES)   // 65536 -> 3 CTAs/SM

__host__ __device__ __forceinline__ int kperm(int k) {   // pair-perm within 8
    return (k & ~7) | (((k & 3) << 1) | ((k & 7) >> 2));
}

// ---------------------------------------------------------------------------
// Scratch — operands stored K-pair-permuted along contraction dims.
// g_K rows (t) kperm'd so S lands pre-permuted; g_VT t-cols kperm'd to match.
// ---------------------------------------------------------------------------
__device__ float g_X  [(size_t)B_ * T_ * C_];
__device__ float g_Q  [(size_t)B_ * T_ * H_];
__device__ float g_K  [(size_t)B_ * T_ * H_];
__device__ float g_VT [(size_t)B_ * H_ * T_];
__device__ float g_S  [(size_t)B_ * T_ * T_];
__device__ float g_WT [3][(size_t)H_ * C_];
__device__ float g_sum[(size_t)B_ * T_];

// ---------------------------------------------------------------------------
// Helpers
// ---------------------------------------------------------------------------
__device__ __forceinline__ uint32_t f2tf32(float f) {
    uint32_t r;
    asm("cvt.rna.tf32.f32 %0, %1;" : "=r"(r) : "f"(f));
    return r;
}
__device__ __forceinline__ float round_tf32(float f) {
    return __uint_as_float(f2tf32(f));
}
__device__ __forceinline__ void mma_tf32(float c[4], const uint32_t a[4],
                                         const uint32_t b[2]) {
    asm volatile(
        "mma.sync.aligned.m16n8k8.row.col.f32.tf32.tf32.f32 "
        "{%0,%1,%2,%3}, {%4,%5,%6,%7}, {%8,%9}, {%0,%1,%2,%3};"
        : "+f"(c[0]), "+f"(c[1]), "+f"(c[2]), "+f"(c[3])
        : "r"(a[0]), "r"(a[1]), "r"(a[2]), "r"(a[3]), "r"(b[0]), "r"(b[1]));
}
__device__ __forceinline__ void cp16(uint32_t d, const void* s) {
    asm volatile("cp.async.cg.shared.global [%0], [%1], 16;" :: "r"(d), "l"(s));
}
__device__ __forceinline__ void cp_commit() { asm volatile("cp.async.commit_group;"); }
__device__ __forceinline__ void cp_wait1()  { asm volatile("cp.async.wait_group 1;"); }
__device__ __forceinline__ void cp_wait0()  { asm volatile("cp.async.wait_group 0;"); }

// ---------------------------------------------------------------------------
// GEMM core. MODE 0: plain (Q/K outputs, optional t-row perm for K)
//            MODE 1: qk fused softmax (exp + causal mask + row-sum atomics)
//            MODE 2: pv deferred normalization
//            MODE 3: V -> VT direct transposed output (t-perm, tf32-rounded)
// 128 thr, 4 warps (2m x 2n, warp 64x64), 2-stage cp.async (3 CTAs/SM).
// ---------------------------------------------------------------------------
template<int MODE>
__device__ __forceinline__ void gemm_core(const float* __restrict__ Ag, int lda,
                                          const float* __restrict__ Bg, int ldb,
                                          float* __restrict__ Cg, int ldc,
                                          int nt, float scale,
                                          const float* __restrict__ rowsum,
                                          float* __restrict__ sumatomic,
                                          int gq0, int gn0,
                                          bool round_out, bool permute_rows)
{
    extern __shared__ char dynsmem[];
    const int tid  = threadIdx.x;
    const int lane = tid & 31;
    const int wid  = tid >> 5;
    const int wm   = wid & 1;
    const int wn   = wid >> 1;
    const int g    = lane >> 2;
    const int t    = lane & 3;

    const uint32_t sb = (uint32_t)__cvta_generic_to_shared(dynsmem);
    const int r0 = tid >> 3;            // 0..15
    const int c4 = (tid & 7) << 2;      // word col 0..28

    auto issue = [&](int s, int buf) {
        const float* Abase = Ag + (size_t)s * BK;
        const float* Bbase = Bg + (size_t)s * BK;
        const uint32_t ab = sb + buf * STAGE_BYTES;
        const uint32_t bb = ab + A_ST_BYTES;
        #pragma unroll
        for (int i = 0; i < 8; i++) {
            const int r  = r0 + 16 * i;
            const int sc = c4 ^ ((r & 3) << 3);
            cp16(ab + r * 128 + sc * 4, Abase + (size_t)r * lda + c4);
            cp16(bb + r * 128 + sc * 4, Bbase + (size_t)r * ldb + c4);
        }
        cp_commit();
    };

    float acc[4][8][4];
    #pragma unroll
    for (int i = 0; i < 4; i++)
        #pragma unroll
        for (int j = 0; j < 8; j++)
            #pragma unroll
            for (int r = 0; r < 4; r++) acc[i][j][r] = 0.0f;

    issue(0, 0);
    if (nt > 1) issue(1, 1);

    const int mwb = wm * 64;
    const int nwb = wn * 64;
    const int swz = (g & 3) << 3;

    for (int s = 0; s < nt; s++) {
        if (s + 1 < nt) cp_wait1(); else cp_wait0();
        __syncthreads();

        const uint32_t* As = (const uint32_t*)(dynsmem + (s & 1) * STAGE_BYTES);
        const uint32_t* Bs = (const uint32_t*)(dynsmem + (s & 1) * STAGE_BYTES + A_ST_BYTES);

        #pragma unroll
        for (int kk8 = 0; kk8 < 4; kk8++) {
            const int cw = (kk8 * 8 + 2 * t) ^ swz;
            uint32_t ar[4][4];
            #pragma unroll
            for (int mf = 0; mf < 4; mf++) {
                const int rA = mwb + mf * 16 + g;
                uint2 v0 = *(const uint2*)&As[rA * 32 + cw];
                uint2 v1 = *(const uint2*)&As[(rA + 8) * 32 + cw];
                ar[mf][0] = v0.x; ar[mf][2] = v0.y;
                ar[mf][1] = v1.x; ar[mf][3] = v1.y;
            }
            uint32_t br[8][2];
            #pragma unroll
            for (int nf = 0; nf < 8; nf++) {
                const int rB = nwb + nf * 8 + g;
                uint2 v = *(const uint2*)&Bs[rB * 32 + cw];
                br[nf][0] = v.x; br[nf][1] = v.y;
            }
            #pragma unroll
            for (int mf = 0; mf < 4; mf++)
                #pragma unroll
                for (int nf = 0; nf < 8; nf++)
                    mma_tf32(acc[mf][nf], ar[mf], br[nf]);
        }

        __syncthreads();
        if (s + 2 < nt) issue(s + 2, s & 1);
    }

    // ---- Epilogue ----
    #pragma unroll
    for (int mf = 0; mf < 4; mf++) {
        const int row = mwb + mf * 16 + g;   // low3 == g

        if (MODE == 1) {
            const int gq = gq0 + row;
            float rs0 = 0.0f, rs1 = 0.0f;
            #pragma unroll
            for (int nf = 0; nf < 8; nf++) {
                const int col = nwb + nf * 8 + 2 * t;
                const int gk0 = gn0 + nwb + nf * 8 + t;
                const int gk1 = gk0 + 4;
                float e0 = (gq     >= gk0) ? __expf(acc[mf][nf][0] * scale) : 0.0f;
                float e1 = (gq     >= gk1) ? __expf(acc[mf][nf][1] * scale) : 0.0f;
                float e2 = (gq + 8 >= gk0) ? __expf(acc[mf][nf][2] * scale) : 0.0f;
                float e3 = (gq + 8 >= gk1) ? __expf(acc[mf][nf][3] * scale) : 0.0f;
                rs0 += e0 + e1;
                rs1 += e2 + e3;
                *(float2*)&Cg[(size_t)row * ldc + col] =
                    make_float2(round_tf32(e0), round_tf32(e1));
                *(float2*)&Cg[(size_t)(row + 8) * ldc + col] =
                    make_float2(round_tf32(e2), round_tf32(e3));
            }
            rs0 += __shfl_xor_sync(0xFFFFFFFFu, rs0, 1);
            rs0 += __shfl_xor_sync(0xFFFFFFFFu, rs0, 2);
            rs1 += __shfl_xor_sync(0xFFFFFFFFu, rs1, 1);
            rs1 += __shfl_xor_sync(0xFFFFFFFFu, rs1, 2);
            if (t == 0) {
                atomicAdd(&sumatomic[row], rs0);
                atomicAdd(&sumatomic[row + 8], rs1);
            }
        } else if (MODE == 3) {
            // V output written transposed into VT: Cg = VT_batch + t0,
            // column index (h) offset by gn0; t index kperm'd.
            const int tp = row - g + kperm(g);
            #pragma unroll
            for (int nf = 0; nf < 8; nf++) {
                const int col = nwb + nf * 8 + 2 * t;
                float v0 = round_tf32(acc[mf][nf][0]);
                float v1 = round_tf32(acc[mf][nf][1]);
                float v2 = round_tf32(acc[mf][nf][2]);
                float v3 = round_tf32(acc[mf][nf][3]);
                Cg[(size_t)(gn0 + col)     * ldc + tp]     = v0;
                Cg[(size_t)(gn0 + col + 1) * ldc + tp]     = v1;
                Cg[(size_t)(gn0 + col)     * ldc + tp + 8] = v2;
                Cg[(size_t)(gn0 + col + 1) * ldc + tp + 8] = v3;
            }
        } else {
            float s0 = scale, s1 = scale;
            if (MODE == 2) {
                s0 = 1.0f / rowsum[row];
                s1 = 1.0f / rowsum[row + 8];
            }
            int rw0 = row, rw1 = row + 8;
            if (MODE == 0 && permute_rows) {     // K output: t-rows kperm'd
                rw0 = (row - g) + kperm(g);
                rw1 = rw0 + 8;
            }
            #pragma unroll
            for (int nf = 0; nf < 8; nf++) {
                const int col = nwb + nf * 8 + 2 * t;
                float v0 = acc[mf][nf][0] * s0, v1 = acc[mf][nf][1] * s0;
                float v2 = acc[mf][nf][2] * s1, v3 = acc[mf][nf][3] * s1;
                if (round_out) {
                    v0 = round_tf32(v0); v1 = round_tf32(v1);
                    v2 = round_tf32(v2); v3 = round_tf32(v3);
                }
                *(float2*)&Cg[(size_t)rw0 * ldc + col] = make_float2(v0, v1);
                *(float2*)&Cg[(size_t)rw1 * ldc + col] = make_float2(v2, v3);
            }
        }
    }
}

// ---------------------------------------------------------------------------
// GEMM wrappers
// ---------------------------------------------------------------------------
__global__ __launch_bounds__(NTHR, 3)
void proj_mma(const float* __restrict__ W0, const float* __restrict__ W1,
              const float* __restrict__ W2)
{
    const int z = blockIdx.z;
    const size_t m0 = (size_t)blockIdx.y * BM;
    const size_t n0 = (size_t)blockIdx.x * BN;
    if (z == 2) {
        const int b  = (int)(m0 >> 11);
        const int t0 = (int)(m0 & (T_ - 1));
        gemm_core<3>(g_X + m0 * C_, C_, W2 + n0 * C_, C_,
                     g_VT + (size_t)b * H_ * T_ + t0, T_, C_ / BK, 1.0f,
                     nullptr, nullptr, 0, (int)n0, true, false);
    } else {
        const float* WT = (z == 0) ? W0 : W1;
        float* out = (z == 0) ? g_Q : g_K;
        gemm_core<0>(g_X + m0 * C_, C_, WT + n0 * C_, C_,
                     out + m0 * H_ + n0, H_, C_ / BK, 1.0f,
                     nullptr, nullptr, 0, 0, true, z == 1);
    }
}

__global__ __launch_bounds__(NTHR, 3)
void qk_mma()
{
    const int kb = blockIdx.x, qb = blockIdx.y;
    if (kb > qb) return;
    const int b = blockIdx.z;
    const size_t q0 = (size_t)qb * 128, n0 = (size_t)kb * 128;
    gemm_core<1>(g_Q + (size_t)b * T_ * H_ + q0 * H_, H_,
                 g_K + (size_t)b * T_ * H_ + n0 * H_, H_,
                 g_S + (size_t)b * T_ * T_ + q0 * T_ + n0, T_,
                 H_ / BK, SCALE_,
                 nullptr, g_sum + (size_t)b * T_ + q0, (int)q0, (int)n0,
                 false, false);
}

__global__ __launch_bounds__(NTHR, 3)
void pv_mma(float* __restrict__ out)
{
    const int nb = blockIdx.x, qb = blockIdx.y, b = blockIdx.z;
    const size_t q0 = (size_t)qb * 128, n0 = (size_t)nb * 128;
    gemm_core<2>(g_S  + (size_t)b * T_ * T_ + q0 * T_, T_,
                 g_VT + (size_t)b * H_ * T_ + n0 * T_, T_,
                 out + (size_t)b * T_ * H_ + q0 * H_ + n0, H_,
                 (qb + 1) * 4, 1.0f,
                 g_sum + (size_t)b * T_ + q0, nullptr, 0, 0,
                 false, false);
}

// ---------------------------------------------------------------------------
// x -> tf32-rounded, C-pair-permuted copy; first 64 blocks also zero g_sum
// ---------------------------------------------------------------------------
__global__ __launch_bounds__(256)
void cvt_x(const float* __restrict__ in)
{
    if (blockIdx.x < (B_ * T_) / 256)
        g_sum[(size_t)blockIdx.x * 256 + threadIdx.x] = 0.0f;
    const size_t i = ((size_t)blockIdx.x * 256 + threadIdx.x) * 4;
    float4 v = *(const float4*)(in + i);
    const size_t base = i & ~(size_t)7;
    const int k0 = (int)(i & 7);
    g_X[base + kperm(k0 + 0)] = round_tf32(v.x);
    g_X[base + kperm(k0 + 1)] = round_tf32(v.y);
    g_X[base + kperm(k0 + 2)] = round_tf32(v.z);
    g_X[base + kperm(k0 + 3)] = round_tf32(v.w);
}

// ---------------------------------------------------------------------------
// W transposes: [C,H] -> [H,C]. C cols pair-permuted; Wq/Wk h rows kperm'd.
// ---------------------------------------------------------------------------
__global__ __launch_bounds__(256)
void transpose_w(const float* __restrict__ Wq, const float* __restrict__ Wk,
                 const float* __restrict__ Wv)
{
    __shared__ float tile[32][33];
    const int z = blockIdx.z;
    const float* I = (z == 0) ? Wq : (z == 1) ? Wk : Wv;
    float* O = g_WT[z];
    const int r0 = blockIdx.y * 32, c0 = blockIdx.x * 32;   // r: C, c: H
    const int tx = threadIdx.x & 31, ty = threadIdx.x >> 5;
    #pragma unroll
    for (int i = 0; i < 32; i += 8)
        tile[ty + i][tx] = I[(size_t)(r0 + ty + i) * H_ + c0 + tx];
    __syncthreads();
    const int fp = kperm(r0 + tx);
    const int hp = (z < 2) ? kperm(ty) : ty;   // h low3 == ty
    #pragma unroll
    for (int i = 0; i < 32; i += 8)
        O[(size_t)(c0 + i + hp) * C_ + fp] = round_tf32(tile[tx][ty + i]);
}

// ---------------------------------------------------------------------------
// Launch
// ---------------------------------------------------------------------------
extern "C" void kernel_launch(void* const* d_in, const int* in_sizes, int n_in,
                              void* d_out, int out_size)
{
    const float* x  = (const float*)d_in[0];
    const float* Wq = (const float*)d_in[1];
    const float* Wk = (const float*)d_in[2];
    const float* Wv = (const float*)d_in[3];
    float* out = (float*)d_out;

    float* wtp;
    cudaGetSymbolAddress((void**)&wtp, g_WT);

    cudaFuncSetAttribute(proj_mma, cudaFuncAttributeMaxDynamicSharedMemorySize, SMEM_TOTAL);
    cudaFuncSetAttribute(qk_mma,   cudaFuncAttributeMaxDynamicSharedMemorySize, SMEM_TOTAL);
    cudaFuncSetAttribute(pv_mma,   cudaFuncAttributeMaxDynamicSharedMemorySize, SMEM_TOTAL);

    cvt_x<<<(B_ * T_ * C_) / (256 * 4), 256>>>(x);

    dim3 gtw(H_ / 32, C_ / 32, 3);
    transpose_w<<<gtw, 256>>>(Wq, Wk, Wv);

    dim3 gproj(H_ / BN, (B_ * T_) / BM, 3);
    proj_mma<<<gproj, NTHR, SMEM_TOTAL>>>(
        wtp, wtp + (size_t)H_ * C_, wtp + 2 * (size_t)H_ * C_);

    dim3 gqk(T_ / 128, T_ / 128, B_);
    qk_mma<<<gqk, NTHR, SMEM_TOTAL>>>();

    dim3 gpv(H_ / 128, T_ / 128, B_);
    pv_mma<<<gpv, NTHR, SMEM_TOTAL>>>(out);
}

// round 12
// speedup vs baseline: 1.5922x; 1.0082x over previous
#include <cuda_runtime.h>
#include <cstdint>
#include <math.h>

#define B_  8
#define T_  2048
#define C_  1024
#define H_  1024
#define SCALE_ (1.0f / 32.0f)

// GEMM tiling: CTA 128x128, 4 warps (2m x 2n), warp 64x64
#define BM 128
#define BN 128
#define BK 32
#define NTHR 128
#define A_ST_BYTES 16384
#define STAGE_BYTES 32768
#define NSTAGES 2
#define SMEM_TOTAL (STAGE_BYTES * NSTAGES)   // 65536 -> 3 CTAs/SM

__host__ __device__ __forceinline__ int kperm(int k) {   // pair-perm within 8
    return (k & ~7) | (((k & 3) << 1) | ((k & 7) >> 2));
}

// ---------------------------------------------------------------------------
// Scratch — operands K-pair-permuted along contraction dims.
// g_K t-rows kperm'd (S lands pre-permuted); g_VT t-cols kperm'd to match.
// ---------------------------------------------------------------------------
__device__ float g_X  [(size_t)B_ * T_ * C_];
__device__ float g_Q  [(size_t)B_ * T_ * H_];
__device__ float g_K  [(size_t)B_ * T_ * H_];
__device__ float g_VT [(size_t)B_ * H_ * T_];
__device__ float g_S  [(size_t)B_ * T_ * T_];
__device__ float g_WT [3][(size_t)H_ * C_];
__device__ float g_sum[(size_t)B_ * T_];

// ---------------------------------------------------------------------------
// Helpers
// ---------------------------------------------------------------------------
__device__ __forceinline__ uint32_t f2tf32(float f) {
    uint32_t r;
    asm("cvt.rna.tf32.f32 %0, %1;" : "=r"(r) : "f"(f));
    return r;
}
__device__ __forceinline__ float round_tf32(float f) {
    return __uint_as_float(f2tf32(f));
}
__device__ __forceinline__ void mma_tf32(float c[4], const uint32_t a[4],
                                         const uint32_t b[2]) {
    asm volatile(
        "mma.sync.aligned.m16n8k8.row.col.f32.tf32.tf32.f32 "
        "{%0,%1,%2,%3}, {%4,%5,%6,%7}, {%8,%9}, {%0,%1,%2,%3};"
        : "+f"(c[0]), "+f"(c[1]), "+f"(c[2]), "+f"(c[3])
        : "r"(a[0]), "r"(a[1]), "r"(a[2]), "r"(a[3]), "r"(b[0]), "r"(b[1]));
}
__device__ __forceinline__ void cp16(uint32_t d, const void* s) {
    asm volatile("cp.async.cg.shared.global [%0], [%1], 16;" :: "r"(d), "l"(s));
}
__device__ __forceinline__ void cp_commit() { asm volatile("cp.async.commit_group;"); }
__device__ __forceinline__ void cp_wait1()  { asm volatile("cp.async.wait_group 1;"); }
__device__ __forceinline__ void cp_wait0()  { asm volatile("cp.async.wait_group 0;"); }

// ---------------------------------------------------------------------------
// GEMM core. MODE 0: plain (Q/K outputs, optional t-row perm for K)
//            MODE 1: qk fused softmax (exp + causal mask + row-sum atomics)
//            MODE 2: pv deferred normalization
//            MODE 3: V -> VT direct transposed output (t-perm, tf32-rounded)
// 128 thr, 4 warps (2m x 2n, warp 64x64), 2-stage cp.async (3 CTAs/SM).
// ---------------------------------------------------------------------------
template<int MODE>
__device__ __forceinline__ void gemm_core(const float* __restrict__ Ag, int lda,
                                          const float* __restrict__ Bg, int ldb,
                                          float* __restrict__ Cg, int ldc,
                                          int nt, float scale,
                                          const float* __restrict__ rowsum,
                                          float* __restrict__ sumatomic,
                                          int gq0, int gn0,
                                          bool round_out, bool permute_rows)
{
    extern __shared__ char dynsmem[];
    const int tid  = threadIdx.x;
    const int lane = tid & 31;
    const int wid  = tid >> 5;
    const int wm   = wid & 1;
    const int wn   = wid >> 1;
    const int g    = lane >> 2;
    const int t    = lane & 3;

    const uint32_t sb = (uint32_t)__cvta_generic_to_shared(dynsmem);
    const int r0 = tid >> 3;            // 0..15
    const int c4 = (tid & 7) << 2;      // word col 0..28

    auto issue = [&](int s, int buf) {
        const float* Abase = Ag + (size_t)s * BK;
        const float* Bbase = Bg + (size_t)s * BK;
        const uint32_t ab = sb + buf * STAGE_BYTES;
        const uint32_t bb = ab + A_ST_BYTES;
        #pragma unroll
        for (int i = 0; i < 8; i++) {
            const int r  = r0 + 16 * i;
            const int sc = c4 ^ ((r & 3) << 3);
            cp16(ab + r * 128 + sc * 4, Abase + (size_t)r * lda + c4);
            cp16(bb + r * 128 + sc * 4, Bbase + (size_t)r * ldb + c4);
        }
        cp_commit();
    };

    float acc[4][8][4];
    #pragma unroll
    for (int i = 0; i < 4; i++)
        #pragma unroll
        for (int j = 0; j < 8; j++)
            #pragma unroll
            for (int r = 0; r < 4; r++) acc[i][j][r] = 0.0f;

    issue(0, 0);
    if (nt > 1) issue(1, 1);

    const int mwb = wm * 64;
    const int nwb = wn * 64;
    const int swz = (g & 3) << 3;

    for (int s = 0; s < nt; s++) {
        if (s + 1 < nt) cp_wait1(); else cp_wait0();
        __syncthreads();

        const uint32_t* As = (const uint32_t*)(dynsmem + (s & 1) * STAGE_BYTES);
        const uint32_t* Bs = (const uint32_t*)(dynsmem + (s & 1) * STAGE_BYTES + A_ST_BYTES);

        #pragma unroll
        for (int kk8 = 0; kk8 < 4; kk8++) {
            const int cw = (kk8 * 8 + 2 * t) ^ swz;
            uint32_t ar[4][4];
            #pragma unroll
            for (int mf = 0; mf < 4; mf++) {
                const int rA = mwb + mf * 16 + g;
                uint2 v0 = *(const uint2*)&As[rA * 32 + cw];
                uint2 v1 = *(const uint2*)&As[(rA + 8) * 32 + cw];
                ar[mf][0] = v0.x; ar[mf][2] = v0.y;
                ar[mf][1] = v1.x; ar[mf][3] = v1.y;
            }
            uint32_t br[8][2];
            #pragma unroll
            for (int nf = 0; nf < 8; nf++) {
                const int rB = nwb + nf * 8 + g;
                uint2 v = *(const uint2*)&Bs[rB * 32 + cw];
                br[nf][0] = v.x; br[nf][1] = v.y;
            }
            #pragma unroll
            for (int mf = 0; mf < 4; mf++)
                #pragma unroll
                for (int nf = 0; nf < 8; nf++)
                    mma_tf32(acc[mf][nf], ar[mf], br[nf]);
        }

        __syncthreads();
        if (s + 2 < nt) issue(s + 2, s & 1);
    }

    // ---- Epilogue ----
    #pragma unroll
    for (int mf = 0; mf < 4; mf++) {
        const int row = mwb + mf * 16 + g;   // low3 == g

        if (MODE == 1) {
            const int gq = gq0 + row;
            float rs0 = 0.0f, rs1 = 0.0f;
            #pragma unroll
            for (int nf = 0; nf < 8; nf++) {
                const int col = nwb + nf * 8 + 2 * t;
                const int gk0 = gn0 + nwb + nf * 8 + t;
                const int gk1 = gk0 + 4;
                float e0 = (gq     >= gk0) ? __expf(acc[mf][nf][0] * scale) : 0.0f;
                float e1 = (gq     >= gk1) ? __expf(acc[mf][nf][1] * scale) : 0.0f;
                float e2 = (gq + 8 >= gk0) ? __expf(acc[mf][nf][2] * scale) : 0.0f;
                float e3 = (gq + 8 >= gk1) ? __expf(acc[mf][nf][3] * scale) : 0.0f;
                rs0 += e0 + e1;
                rs1 += e2 + e3;
                *(float2*)&Cg[(size_t)row * ldc + col] =
                    make_float2(round_tf32(e0), round_tf32(e1));
                *(float2*)&Cg[(size_t)(row + 8) * ldc + col] =
                    make_float2(round_tf32(e2), round_tf32(e3));
            }
            rs0 += __shfl_xor_sync(0xFFFFFFFFu, rs0, 1);
            rs0 += __shfl_xor_sync(0xFFFFFFFFu, rs0, 2);
            rs1 += __shfl_xor_sync(0xFFFFFFFFu, rs1, 1);
            rs1 += __shfl_xor_sync(0xFFFFFFFFu, rs1, 2);
            if (t == 0) {
                atomicAdd(&sumatomic[row], rs0);
                atomicAdd(&sumatomic[row + 8], rs1);
            }
        } else if (MODE == 3) {
            const int tp = row - g + kperm(g);
            #pragma unroll
            for (int nf = 0; nf < 8; nf++) {
                const int col = nwb + nf * 8 + 2 * t;
                float v0 = round_tf32(acc[mf][nf][0]);
                float v1 = round_tf32(acc[mf][nf][1]);
                float v2 = round_tf32(acc[mf][nf][2]);
                float v3 = round_tf32(acc[mf][nf][3]);
                Cg[(size_t)(gn0 + col)     * ldc + tp]     = v0;
                Cg[(size_t)(gn0 + col + 1) * ldc + tp]     = v1;
                Cg[(size_t)(gn0 + col)     * ldc + tp + 8] = v2;
                Cg[(size_t)(gn0 + col + 1) * ldc + tp + 8] = v3;
            }
        } else {
            float s0 = scale, s1 = scale;
            if (MODE == 2) {
                s0 = 1.0f / rowsum[row];
                s1 = 1.0f / rowsum[row + 8];
            }
            int rw0 = row, rw1 = row + 8;
            if (MODE == 0 && permute_rows) {
                rw0 = (row - g) + kperm(g);
                rw1 = rw0 + 8;
            }
            #pragma unroll
            for (int nf = 0; nf < 8; nf++) {
                const int col = nwb + nf * 8 + 2 * t;
                float v0 = acc[mf][nf][0] * s0, v1 = acc[mf][nf][1] * s0;
                float v2 = acc[mf][nf][2] * s1, v3 = acc[mf][nf][3] * s1;
                if (round_out) {
                    v0 = round_tf32(v0); v1 = round_tf32(v1);
                    v2 = round_tf32(v2); v3 = round_tf32(v3);
                }
                *(float2*)&Cg[(size_t)rw0 * ldc + col] = make_float2(v0, v1);
                *(float2*)&Cg[(size_t)rw1 * ldc + col] = make_float2(v2, v3);
            }
        }
    }
}

// ---------------------------------------------------------------------------
// Q/K projections only (z = 0,1)
// ---------------------------------------------------------------------------
__global__ __launch_bounds__(NTHR, 3)
void proj_qk(const float* __restrict__ W0, const float* __restrict__ W1)
{
    const int z = blockIdx.z;
    const float* WT = (z == 0) ? W0 : W1;
    float* out = (z == 0) ? g_Q : g_K;
    const size_t m0 = (size_t)blockIdx.y * BM;
    const size_t n0 = (size_t)blockIdx.x * BN;
    gemm_core<0>(g_X + m0 * C_, C_, WT + n0 * C_, C_,
                 out + m0 * H_ + n0, H_, C_ / BK, 1.0f,
                 nullptr, nullptr, 0, 0, true, z == 1);
}

// ---------------------------------------------------------------------------
// Merged launch: 1088 triangular qk tiles + 1024 V-projection tiles,
// interleaved in 33-block groups (17 qk + 16 projV). Grid.x = 2112.
// ---------------------------------------------------------------------------
__global__ __launch_bounds__(NTHR, 3)
void qk_projv(const float* __restrict__ W2)
{
    const int idx   = blockIdx.x;
    const int group = idx / 33;
    const int pos   = idx % 33;

    if (pos < 17) {
        // ---- qk tile ----
        const int i = group * 17 + pos;        // 0..1087
        const int b = i / 136;
        const int r = i % 136;
        int qb = (int)((sqrtf(8.0f * (float)r + 1.0f) - 1.0f) * 0.5f);
        while ((qb + 1) * (qb + 2) / 2 <= r) qb++;
        while (qb * (qb + 1) / 2 > r)       qb--;
        const int kb = r - qb * (qb + 1) / 2;

        const size_t q0 = (size_t)qb * 128, n0 = (size_t)kb * 128;
        gemm_core<1>(g_Q + (size_t)b * T_ * H_ + q0 * H_, H_,
                     g_K + (size_t)b * T_ * H_ + n0 * H_, H_,
                     g_S + (size_t)b * T_ * T_ + q0 * T_ + n0, T_,
                     H_ / BK, SCALE_,
                     nullptr, g_sum + (size_t)b * T_ + q0, (int)q0, (int)n0,
                     false, false);
    } else {
        // ---- V projection tile (writes VT directly) ----
        const int j  = group * 16 + (pos - 17);   // 0..1023
        const int nb = j & 7;
        const int mb = j >> 3;
        const size_t m0 = (size_t)mb * BM;
        const size_t n0 = (size_t)nb * BN;
        const int b  = (int)(m0 >> 11);
        const int t0 = (int)(m0 & (T_ - 1));
        gemm_core<3>(g_X + m0 * C_, C_, W2 + n0 * C_, C_,
                     g_VT + (size_t)b * H_ * T_ + t0, T_, C_ / BK, 1.0f,
                     nullptr, nullptr, 0, (int)n0, true, false);
    }
}

__global__ __launch_bounds__(NTHR, 3)
void pv_mma(float* __restrict__ out)
{
    const int nb = blockIdx.x, qb = blockIdx.y, b = blockIdx.z;
    const size_t q0 = (size_t)qb * 128, n0 = (size_t)nb * 128;
    gemm_core<2>(g_S  + (size_t)b * T_ * T_ + q0 * T_, T_,
                 g_VT + (size_t)b * H_ * T_ + n0 * T_, T_,
                 out + (size_t)b * T_ * H_ + q0 * H_ + n0, H_,
                 (qb + 1) * 4, 1.0f,
                 g_sum + (size_t)b * T_ + q0, nullptr, 0, 0,
                 false, false);
}

// ---------------------------------------------------------------------------
// x -> tf32-rounded, C-pair-permuted copy; first 64 blocks also zero g_sum
// ---------------------------------------------------------------------------
__global__ __launch_bounds__(256)
void cvt_x(const float* __restrict__ in)
{
    if (blockIdx.x < (B_ * T_) / 256)
        g_sum[(size_t)blockIdx.x * 256 + threadIdx.x] = 0.0f;
    const size_t i = ((size_t)blockIdx.x * 256 + threadIdx.x) * 4;
    float4 v = *(const float4*)(in + i);
    const size_t base = i & ~(size_t)7;
    const int k0 = (int)(i & 7);
    g_X[base + kperm(k0 + 0)] = round_tf32(v.x);
    g_X[base + kperm(k0 + 1)] = round_tf32(v.y);
    g_X[base + kperm(k0 + 2)] = round_tf32(v.z);
    g_X[base + kperm(k0 + 3)] = round_tf32(v.w);
}

// ---------------------------------------------------------------------------
// W transposes: [C,H] -> [H,C]. C cols pair-permuted; Wq/Wk h rows kperm'd.
// ---------------------------------------------------------------------------
__global__ __launch_bounds__(256)
void transpose_w(const float* __restrict__ Wq, const float* __restrict__ Wk,
                 const float* __restrict__ Wv)
{
    __shared__ float tile[32][33];
    const int z = blockIdx.z;
    const float* I = (z == 0) ? Wq : (z == 1) ? Wk : Wv;
    float* O = g_WT[z];
    const int r0 = blockIdx.y * 32, c0 = blockIdx.x * 32;
    const int tx = threadIdx.x & 31, ty = threadIdx.x >> 5;
    #pragma unroll
    for (int i = 0; i < 32; i += 8)
        tile[ty + i][tx] = I[(size_t)(r0 + ty + i) * H_ + c0 + tx];
    __syncthreads();
    const int fp = kperm(r0 + tx);
    const int hp = (z < 2) ? kperm(ty) : ty;
    #pragma unroll
    for (int i = 0; i < 32; i += 8)
        O[(size_t)(c0 + i + hp) * C_ + fp] = round_tf32(tile[tx][ty + i]);
}

// ---------------------------------------------------------------------------
// Launch
// ---------------------------------------------------------------------------
extern "C" void kernel_launch(void* const* d_in, const int* in_sizes, int n_in,
                              void* d_out, int out_size)
{
    const float* x  = (const float*)d_in[0];
    const float* Wq = (const float*)d_in[1];
    const float* Wk = (const float*)d_in[2];
    const float* Wv = (const float*)d_in[3];
    float* out = (float*)d_out;

    float* wtp;
    cudaGetSymbolAddress((void**)&wtp, g_WT);

    cudaFuncSetAttribute(proj_qk,  cudaFuncAttributeMaxDynamicSharedMemorySize, SMEM_TOTAL);
    cudaFuncSetAttribute(qk_projv, cudaFuncAttributeMaxDynamicSharedMemorySize, SMEM_TOTAL);
    cudaFuncSetAttribute(pv_mma,   cudaFuncAttributeMaxDynamicSharedMemorySize, SMEM_TOTAL);

    cvt_x<<<(B_ * T_ * C_) / (256 * 4), 256>>>(x);

    dim3 gtw(H_ / 32, C_ / 32, 3);
    transpose_w<<<gtw, 256>>>(Wq, Wk, Wv);

    // Q/K projections
    dim3 gproj(H_ / BN, (B_ * T_) / BM, 2);
    proj_qk<<<gproj, NTHR, SMEM_TOTAL>>>(wtp, wtp + (size_t)H_ * C_);

    // Merged: triangular qk (1088) + V projection (1024), interleaved
    qk_projv<<<2112, NTHR, SMEM_TOTAL>>>(wtp + 2 * (size_t)H_ * C_);

    // pv with deferred normalization
    dim3 gpv(H_ / 128, T_ / 128, B_);
    pv_mma<<<gpv, NTHR, SMEM_TOTAL>>>(out);
}

// round 13
// speedup vs baseline: 1.6851x; 1.0583x over previous
#include <cuda_runtime.h>
#include <cstdint>
#include <math.h>

#define B_  8
#define T_  2048
#define C_  1024
#define H_  1024
#define SCALE_ (1.0f / 32.0f)

// GEMM tiling: CTA 128x128, 4 warps (2m x 2n), warp 64x64
#define BM 128
#define BN 128
#define BK 32
#define NTHR 128
#define A_ST_BYTES 16384
#define STAGE_BYTES 32768
#define NSTAGES 2
#define SMEM_TOTAL (STAGE_BYTES * NSTAGES)   // 65536 -> 3 CTAs/SM

__host__ __device__ __forceinline__ int kperm(int k) {   // pair-perm within 8
    return (k & ~7) | (((k & 3) << 1) | ((k & 7) >> 2));
}

// ---------------------------------------------------------------------------
// Scratch — operands K-pair-permuted along contraction dims.
// g_K t-rows kperm'd (S lands pre-permuted); g_VT t-cols kperm'd to match.
// ---------------------------------------------------------------------------
__device__ float g_X  [(size_t)B_ * T_ * C_];
__device__ float g_Q  [(size_t)B_ * T_ * H_];
__device__ float g_K  [(size_t)B_ * T_ * H_];
__device__ float g_VT [(size_t)B_ * H_ * T_];
__device__ float g_S  [(size_t)B_ * T_ * T_];
__device__ float g_WT [3][(size_t)H_ * C_];
__device__ float g_sum[(size_t)B_ * T_];

// ---------------------------------------------------------------------------
// Helpers
// ---------------------------------------------------------------------------
__device__ __forceinline__ uint32_t f2tf32(float f) {
    uint32_t r;
    asm("cvt.rna.tf32.f32 %0, %1;" : "=r"(r) : "f"(f));
    return r;
}
__device__ __forceinline__ float round_tf32(float f) {
    return __uint_as_float(f2tf32(f));
}
__device__ __forceinline__ void mma_tf32(float c[4], const uint32_t a[4],
                                         const uint32_t b[2]) {
    asm volatile(
        "mma.sync.aligned.m16n8k8.row.col.f32.tf32.tf32.f32 "
        "{%0,%1,%2,%3}, {%4,%5,%6,%7}, {%8,%9}, {%0,%1,%2,%3};"
        : "+f"(c[0]), "+f"(c[1]), "+f"(c[2]), "+f"(c[3])
        : "r"(a[0]), "r"(a[1]), "r"(a[2]), "r"(a[3]), "r"(b[0]), "r"(b[1]));
}
__device__ __forceinline__ void cp16(uint32_t d, const void* s) {
    asm volatile("cp.async.cg.shared.global [%0], [%1], 16;" :: "r"(d), "l"(s));
}
__device__ __forceinline__ void cp_commit() { asm volatile("cp.async.commit_group;"); }
__device__ __forceinline__ void cp_wait1()  { asm volatile("cp.async.wait_group 1;"); }
__device__ __forceinline__ void cp_wait0()  { asm volatile("cp.async.wait_group 0;"); }

// ---------------------------------------------------------------------------
// GEMM core. MODE 0: plain (Q/K outputs, optional t-row perm for K)
//            MODE 1: qk fused softmax (exp + causal mask + row-sum atomics)
//            MODE 2: pv deferred normalization
//            MODE 3: V -> VT direct transposed output (t-perm, tf32-rounded)
// 128 thr, 4 warps (2m x 2n, warp 64x64), 2-stage cp.async (3 CTAs/SM).
// ---------------------------------------------------------------------------
template<int MODE>
__device__ __forceinline__ void gemm_core(const float* __restrict__ Ag, int lda,
                                          const float* __restrict__ Bg, int ldb,
                                          float* __restrict__ Cg, int ldc,
                                          int nt, float scale,
                                          const float* __restrict__ rowsum,
                                          float* __restrict__ sumatomic,
                                          int gq0, int gn0,
                                          bool round_out, bool permute_rows)
{
    extern __shared__ char dynsmem[];
    const int tid  = threadIdx.x;
    const int lane = tid & 31;
    const int wid  = tid >> 5;
    const int wm   = wid & 1;
    const int wn   = wid >> 1;
    const int g    = lane >> 2;
    const int t    = lane & 3;

    const uint32_t sb = (uint32_t)__cvta_generic_to_shared(dynsmem);
    const int r0 = tid >> 3;            // 0..15
    const int c4 = (tid & 7) << 2;      // word col 0..28

    auto issue = [&](int s, int buf) {
        const float* Abase = Ag + (size_t)s * BK;
        const float* Bbase = Bg + (size_t)s * BK;
        const uint32_t ab = sb + buf * STAGE_BYTES;
        const uint32_t bb = ab + A_ST_BYTES;
        #pragma unroll
        for (int i = 0; i < 8; i++) {
            const int r  = r0 + 16 * i;
            const int sc = c4 ^ ((r & 3) << 3);
            cp16(ab + r * 128 + sc * 4, Abase + (size_t)r * lda + c4);
            cp16(bb + r * 128 + sc * 4, Bbase + (size_t)r * ldb + c4);
        }
        cp_commit();
    };

    float acc[4][8][4];
    #pragma unroll
    for (int i = 0; i < 4; i++)
        #pragma unroll
        for (int j = 0; j < 8; j++)
            #pragma unroll
            for (int r = 0; r < 4; r++) acc[i][j][r] = 0.0f;

    issue(0, 0);
    if (nt > 1) issue(1, 1);

    const int mwb = wm * 64;
    const int nwb = wn * 64;
    const int swz = (g & 3) << 3;

    for (int s = 0; s < nt; s++) {
        if (s + 1 < nt) cp_wait1(); else cp_wait0();
        __syncthreads();

        const uint32_t* As = (const uint32_t*)(dynsmem + (s & 1) * STAGE_BYTES);
        const uint32_t* Bs = (const uint32_t*)(dynsmem + (s & 1) * STAGE_BYTES + A_ST_BYTES);

        #pragma unroll
        for (int kk8 = 0; kk8 < 4; kk8++) {
            const int cw = (kk8 * 8 + 2 * t) ^ swz;
            uint32_t ar[4][4];
            #pragma unroll
            for (int mf = 0; mf < 4; mf++) {
                const int rA = mwb + mf * 16 + g;
                uint2 v0 = *(const uint2*)&As[rA * 32 + cw];
                uint2 v1 = *(const uint2*)&As[(rA + 8) * 32 + cw];
                ar[mf][0] = v0.x; ar[mf][2] = v0.y;
                ar[mf][1] = v1.x; ar[mf][3] = v1.y;
            }
            uint32_t br[8][2];
            #pragma unroll
            for (int nf = 0; nf < 8; nf++) {
                const int rB = nwb + nf * 8 + g;
                uint2 v = *(const uint2*)&Bs[rB * 32 + cw];
                br[nf][0] = v.x; br[nf][1] = v.y;
            }
            #pragma unroll
            for (int mf = 0; mf < 4; mf++)
                #pragma unroll
                for (int nf = 0; nf < 8; nf++)
                    mma_tf32(acc[mf][nf], ar[mf], br[nf]);
        }

        __syncthreads();
        if (s + 2 < nt) issue(s + 2, s & 1);
    }

    // ---- Epilogue ----
    #pragma unroll
    for (int mf = 0; mf < 4; mf++) {
        const int row = mwb + mf * 16 + g;   // low3 == g

        if (MODE == 1) {
            const int gq = gq0 + row;
            float rs0 = 0.0f, rs1 = 0.0f;
            #pragma unroll
            for (int nf = 0; nf < 8; nf++) {
                const int col = nwb + nf * 8 + 2 * t;
                const int gk0 = gn0 + nwb + nf * 8 + t;
                const int gk1 = gk0 + 4;
                float e0 = (gq     >= gk0) ? __expf(acc[mf][nf][0] * scale) : 0.0f;
                float e1 = (gq     >= gk1) ? __expf(acc[mf][nf][1] * scale) : 0.0f;
                float e2 = (gq + 8 >= gk0) ? __expf(acc[mf][nf][2] * scale) : 0.0f;
                float e3 = (gq + 8 >= gk1) ? __expf(acc[mf][nf][3] * scale) : 0.0f;
                rs0 += e0 + e1;
                rs1 += e2 + e3;
                *(float2*)&Cg[(size_t)row * ldc + col] =
                    make_float2(round_tf32(e0), round_tf32(e1));
                *(float2*)&Cg[(size_t)(row + 8) * ldc + col] =
                    make_float2(round_tf32(e2), round_tf32(e3));
            }
            rs0 += __shfl_xor_sync(0xFFFFFFFFu, rs0, 1);
            rs0 += __shfl_xor_sync(0xFFFFFFFFu, rs0, 2);
            rs1 += __shfl_xor_sync(0xFFFFFFFFu, rs1, 1);
            rs1 += __shfl_xor_sync(0xFFFFFFFFu, rs1, 2);
            if (t == 0) {
                atomicAdd(&sumatomic[row], rs0);
                atomicAdd(&sumatomic[row + 8], rs1);
            }
        } else if (MODE == 3) {
            const int tp = row - g + kperm(g);
            #pragma unroll
            for (int nf = 0; nf < 8; nf++) {
                const int col = nwb + nf * 8 + 2 * t;
                float v0 = round_tf32(acc[mf][nf][0]);
                float v1 = round_tf32(acc[mf][nf][1]);
                float v2 = round_tf32(acc[mf][nf][2]);
                float v3 = round_tf32(acc[mf][nf][3]);
                Cg[(size_t)(gn0 + col)     * ldc + tp]     = v0;
                Cg[(size_t)(gn0 + col + 1) * ldc + tp]     = v1;
                Cg[(size_t)(gn0 + col)     * ldc + tp + 8] = v2;
                Cg[(size_t)(gn0 + col + 1) * ldc + tp + 8] = v3;
            }
        } else {
            float s0 = scale, s1 = scale;
            if (MODE == 2) {
                s0 = 1.0f / rowsum[row];
                s1 = 1.0f / rowsum[row + 8];
            }
            int rw0 = row, rw1 = row + 8;
            if (MODE == 0 && permute_rows) {
                rw0 = (row - g) + kperm(g);
                rw1 = rw0 + 8;
            }
            #pragma unroll
            for (int nf = 0; nf < 8; nf++) {
                const int col = nwb + nf * 8 + 2 * t;
                float v0 = acc[mf][nf][0] * s0, v1 = acc[mf][nf][1] * s0;
                float v2 = acc[mf][nf][2] * s1, v3 = acc[mf][nf][3] * s1;
                if (round_out) {
                    v0 = round_tf32(v0); v1 = round_tf32(v1);
                    v2 = round_tf32(v2); v3 = round_tf32(v3);
                }
                *(float2*)&Cg[(size_t)rw0 * ldc + col] = make_float2(v0, v1);
                *(float2*)&Cg[(size_t)rw1 * ldc + col] = make_float2(v2, v3);
            }
        }
    }
}

// ---------------------------------------------------------------------------
// Q/K projections only (z = 0,1)
// ---------------------------------------------------------------------------
__global__ __launch_bounds__(NTHR, 3)
void proj_qk(const float* __restrict__ W0, const float* __restrict__ W1)
{
    const int z = blockIdx.z;
    const float* WT = (z == 0) ? W0 : W1;
    float* out = (z == 0) ? g_Q : g_K;
    const size_t m0 = (size_t)blockIdx.y * BM;
    const size_t n0 = (size_t)blockIdx.x * BN;
    gemm_core<0>(g_X + m0 * C_, C_, WT + n0 * C_, C_,
                 out + m0 * H_ + n0, H_, C_ / BK, 1.0f,
                 nullptr, nullptr, 0, 0, true, z == 1);
}

// ---------------------------------------------------------------------------
// Merged launch: 1088 triangular qk tiles (big-qb first) + 1024 V-projection
// tiles, interleaved in 33-block groups (17 qk + 16 projV). Grid.x = 2112.
// ---------------------------------------------------------------------------
__global__ __launch_bounds__(NTHR, 3)
void qk_projv(const float* __restrict__ W2)
{
    const int idx   = blockIdx.x;
    const int group = idx / 33;
    const int pos   = idx % 33;

    if (pos < 17) {
        // ---- qk tile, descending qb (big tiles scheduled first) ----
        const int i = group * 17 + pos;        // 0..1087
        const int b = i / 136;
        const int r = 135 - (i % 136);         // reverse -> qb descends
        int qb = (int)((sqrtf(8.0f * (float)r + 1.0f) - 1.0f) * 0.5f);
        while ((qb + 1) * (qb + 2) / 2 <= r) qb++;
        while (qb * (qb + 1) / 2 > r)       qb--;
        const int kb = r - qb * (qb + 1) / 2;

        const size_t q0 = (size_t)qb * 128, n0 = (size_t)kb * 128;
        gemm_core<1>(g_Q + (size_t)b * T_ * H_ + q0 * H_, H_,
                     g_K + (size_t)b * T_ * H_ + n0 * H_, H_,
                     g_S + (size_t)b * T_ * T_ + q0 * T_ + n0, T_,
                     H_ / BK, SCALE_,
                     nullptr, g_sum + (size_t)b * T_ + q0, (int)q0, (int)n0,
                     false, false);
    } else {
        // ---- V projection tile (writes VT directly) ----
        const int j  = group * 16 + (pos - 17);   // 0..1023
        const int nb = j & 7;
        const int mb = j >> 3;
        const size_t m0 = (size_t)mb * BM;
        const size_t n0 = (size_t)nb * BN;
        const int b  = (int)(m0 >> 11);
        const int t0 = (int)(m0 & (T_ - 1));
        gemm_core<3>(g_X + m0 * C_, C_, W2 + n0 * C_, C_,
                     g_VT + (size_t)b * H_ * T_ + t0, T_, C_ / BK, 1.0f,
                     nullptr, nullptr, 0, (int)n0, true, false);
    }
}

// ---------------------------------------------------------------------------
// pv: 1D grid 1024, qb DESCENDING (longest-processing-time-first)
// ---------------------------------------------------------------------------
__global__ __launch_bounds__(NTHR, 3)
void pv_mma(float* __restrict__ out)
{
    const int idx = blockIdx.x;
    const int qb  = 15 - (idx >> 6);     // 64 CTAs per qb; qb=15 first
    const int rem = idx & 63;
    const int b   = rem >> 3;
    const int nb  = rem & 7;
    const size_t q0 = (size_t)qb * 128, n0 = (size_t)nb * 128;
    gemm_core<2>(g_S  + (size_t)b * T_ * T_ + q0 * T_, T_,
                 g_VT + (size_t)b * H_ * T_ + n0 * T_, T_,
                 out + (size_t)b * T_ * H_ + q0 * H_ + n0, H_,
                 (qb + 1) * 4, 1.0f,
                 g_sum + (size_t)b * T_ + q0, nullptr, 0, 0,
                 false, false);
}

// ---------------------------------------------------------------------------
// prep: blocks [0, 16384) convert x (tf32 + C-perm; first 64 also zero g_sum);
//       blocks [16384, 19456) transpose W (C cols perm; Wq/Wk h rows perm)
// ---------------------------------------------------------------------------
__global__ __launch_bounds__(256)
void prep(const float* __restrict__ x, const float* __restrict__ Wq,
          const float* __restrict__ Wk, const float* __restrict__ Wv)
{
    __shared__ float tile[32][33];
    const int bid = blockIdx.x;

    if (bid < 16384) {
        if (bid < (B_ * T_) / 256)
            g_sum[(size_t)bid * 256 + threadIdx.x] = 0.0f;
        const size_t i = ((size_t)bid * 256 + threadIdx.x) * 4;
        float4 v = *(const float4*)(x + i);
        const size_t base = i & ~(size_t)7;
        const int k0 = (int)(i & 7);
        g_X[base + kperm(k0 + 0)] = round_tf32(v.x);
        g_X[base + kperm(k0 + 1)] = round_tf32(v.y);
        g_X[base + kperm(k0 + 2)] = round_tf32(v.z);
        g_X[base + kperm(k0 + 3)] = round_tf32(v.w);
    } else {
        const int j = bid - 16384;             // 0..3071
        const int z = j / 1024;
        const int rest = j % 1024;
        const int bx = rest & 31;              // H/32 tiles
        const int by = rest >> 5;              // C/32 tiles
        const float* I = (z == 0) ? Wq : (z == 1) ? Wk : Wv;
        float* O = g_WT[z];
        const int r0 = by * 32, c0 = bx * 32;  // r: C, c: H
        const int tx = threadIdx.x & 31, ty = threadIdx.x >> 5;
        #pragma unroll
        for (int i = 0; i < 32; i += 8)
            tile[ty + i][tx] = I[(size_t)(r0 + ty + i) * H_ + c0 + tx];
        __syncthreads();
        const int fp = kperm(r0 + tx);
        const int hp = (z < 2) ? kperm(ty) : ty;
        #pragma unroll
        for (int i = 0; i < 32; i += 8)
            O[(size_t)(c0 + i + hp) * C_ + fp] = round_tf32(tile[tx][ty + i]);
    }
}

// ---------------------------------------------------------------------------
// Launch
// ---------------------------------------------------------------------------
extern "C" void kernel_launch(void* const* d_in, const int* in_sizes, int n_in,
                              void* d_out, int out_size)
{
    const float* x  = (const float*)d_in[0];
    const float* Wq = (const float*)d_in[1];
    const float* Wk = (const float*)d_in[2];
    const float* Wv = (const float*)d_in[3];
    float* out = (float*)d_out;

    float* wtp;
    cudaGetSymbolAddress((void**)&wtp, g_WT);

    cudaFuncSetAttribute(proj_qk,  cudaFuncAttributeMaxDynamicSharedMemorySize, SMEM_TOTAL);
    cudaFuncSetAttribute(qk_projv, cudaFuncAttributeMaxDynamicSharedMemorySize, SMEM_TOTAL);
    cudaFuncSetAttribute(pv_mma,   cudaFuncAttributeMaxDynamicSharedMemorySize, SMEM_TOTAL);

    // x convert + W transposes in one launch
    prep<<<16384 + 3072, 256>>>(x, Wq, Wk, Wv);

    // Q/K projections
    dim3 gproj(H_ / BN, (B_ * T_) / BM, 2);
    proj_qk<<<gproj, NTHR, SMEM_TOTAL>>>(wtp, wtp + (size_t)H_ * C_);

    // Merged: triangular qk (1088, big-first) + V projection (1024)
    qk_projv<<<2112, NTHR, SMEM_TOTAL>>>(wtp + 2 * (size_t)H_ * C_);

    // pv with deferred normalization, longest tiles first
    pv_mma<<<1024, NTHR, SMEM_TOTAL>>>(out);
}